// round 1
// baseline (speedup 1.0000x reference)
#include <cuda_runtime.h>
#include <math.h>

#define N_TOKEN 4096
#define DIM 1024
#define BM 128
#define BN 128
#define BK 16
#define PAD 4   // keeps 16B alignment (row stride 132 floats = 528B = 33*16B)

// Scratch (allocation-free rule: __device__ globals)
__device__ float g_Q[N_TOKEN * DIM];
__device__ float g_K[N_TOKEN * DIM];
__device__ float g_V[N_TOKEN * DIM];
__device__ float g_S[N_TOKEN * N_TOKEN];   // 64 MB score/prob matrix (in-place softmax)

// ---------------------------------------------------------------------------
// Kernel 1: fused QKV projection.  out = x @ W + b   (NN GEMM, all dims 1024/4096)
// blockIdx.z selects which of Q/K/V.
// ---------------------------------------------------------------------------
__global__ __launch_bounds__(256) void proj_kernel(
    const float* __restrict__ x,
    const float* __restrict__ Wq, const float* __restrict__ bq,
    const float* __restrict__ Wk, const float* __restrict__ bk,
    const float* __restrict__ Wv, const float* __restrict__ bv)
{
    __shared__ float As[BK][BM + PAD];
    __shared__ float Bs[BK][BN + PAD];

    const float* W; const float* bias; float* out;
    if (blockIdx.z == 0)      { W = Wq; bias = bq; out = g_Q; }
    else if (blockIdx.z == 1) { W = Wk; bias = bk; out = g_K; }
    else                      { W = Wv; bias = bv; out = g_V; }

    const int row0 = blockIdx.y * BM;
    const int col0 = blockIdx.x * BN;
    const int tid  = threadIdx.x;
    const int tx   = tid & 15;
    const int ty   = tid >> 4;

    float acc[8][8];
#pragma unroll
    for (int y = 0; y < 8; y++)
#pragma unroll
        for (int xx = 0; xx < 8; xx++) acc[y][xx] = 0.f;

    for (int k0 = 0; k0 < DIM; k0 += BK) {
        // A tile: x[row0+r][k0+kk]  (float4 along k, store transposed)
#pragma unroll
        for (int i = 0; i < 2; i++) {
            int idx = tid + i * 256;          // 0..511
            int r   = idx >> 2;
            int kq  = idx & 3;
            float4 v = *(const float4*)(x + (size_t)(row0 + r) * DIM + k0 + kq * 4);
            As[kq * 4 + 0][r] = v.x;
            As[kq * 4 + 1][r] = v.y;
            As[kq * 4 + 2][r] = v.z;
            As[kq * 4 + 3][r] = v.w;
        }
        // B tile: W[k0+kk][col0+c]  (float4 along columns, direct store)
#pragma unroll
        for (int i = 0; i < 2; i++) {
            int idx = tid + i * 256;
            int kk  = idx >> 5;
            int cq  = idx & 31;
            *(float4*)&Bs[kk][cq * 4] =
                *(const float4*)(W + (size_t)(k0 + kk) * DIM + col0 + cq * 4);
        }
        __syncthreads();

#pragma unroll
        for (int k = 0; k < BK; k++) {
            float4 a0 = *(float4*)&As[k][ty * 8];
            float4 a1 = *(float4*)&As[k][ty * 8 + 4];
            float4 b0 = *(float4*)&Bs[k][tx * 8];
            float4 b1 = *(float4*)&Bs[k][tx * 8 + 4];
            float a[8] = {a0.x, a0.y, a0.z, a0.w, a1.x, a1.y, a1.z, a1.w};
            float b[8] = {b0.x, b0.y, b0.z, b0.w, b1.x, b1.y, b1.z, b1.w};
#pragma unroll
            for (int y = 0; y < 8; y++)
#pragma unroll
                for (int xx = 0; xx < 8; xx++)
                    acc[y][xx] = fmaf(a[y], b[xx], acc[y][xx]);
        }
        __syncthreads();
    }

    // epilogue with bias
#pragma unroll
    for (int y = 0; y < 8; y++) {
        int row = row0 + ty * 8 + y;
        float* dst = out + (size_t)row * DIM + col0 + tx * 8;
        const float* bp = bias + col0 + tx * 8;
        float4 o0 = {acc[y][0] + bp[0], acc[y][1] + bp[1], acc[y][2] + bp[2], acc[y][3] + bp[3]};
        float4 o1 = {acc[y][4] + bp[4], acc[y][5] + bp[5], acc[y][6] + bp[6], acc[y][7] + bp[7]};
        *(float4*)dst       = o0;
        *(float4*)(dst + 4) = o1;
    }
}

// ---------------------------------------------------------------------------
// Kernel 2: S = (Q @ K^T) * scale, lower-triangular blocks only (NT GEMM)
// ---------------------------------------------------------------------------
__global__ __launch_bounds__(256) void score_kernel()
{
    const int ct = blockIdx.x;   // key block
    const int rt = blockIdx.y;   // query block
    if (ct > rt) return;         // strictly-upper blocks never read

    __shared__ float As[BK][BM + PAD];
    __shared__ float Bs[BK][BN + PAD];

    const int row0 = rt * BM;
    const int col0 = ct * BN;
    const int tid  = threadIdx.x;
    const int tx   = tid & 15;
    const int ty   = tid >> 4;

    float acc[8][8];
#pragma unroll
    for (int y = 0; y < 8; y++)
#pragma unroll
        for (int xx = 0; xx < 8; xx++) acc[y][xx] = 0.f;

    for (int k0 = 0; k0 < DIM; k0 += BK) {
#pragma unroll
        for (int i = 0; i < 2; i++) {
            int idx = tid + i * 256;
            int r   = idx >> 2;
            int kq  = idx & 3;
            float4 v = *(const float4*)(g_Q + (size_t)(row0 + r) * DIM + k0 + kq * 4);
            As[kq * 4 + 0][r] = v.x;
            As[kq * 4 + 1][r] = v.y;
            As[kq * 4 + 2][r] = v.z;
            As[kq * 4 + 3][r] = v.w;
        }
#pragma unroll
        for (int i = 0; i < 2; i++) {
            int idx = tid + i * 256;
            int r   = idx >> 2;
            int kq  = idx & 3;
            float4 v = *(const float4*)(g_K + (size_t)(col0 + r) * DIM + k0 + kq * 4);
            Bs[kq * 4 + 0][r] = v.x;
            Bs[kq * 4 + 1][r] = v.y;
            Bs[kq * 4 + 2][r] = v.z;
            Bs[kq * 4 + 3][r] = v.w;
        }
        __syncthreads();

#pragma unroll
        for (int k = 0; k < BK; k++) {
            float4 a0 = *(float4*)&As[k][ty * 8];
            float4 a1 = *(float4*)&As[k][ty * 8 + 4];
            float4 b0 = *(float4*)&Bs[k][tx * 8];
            float4 b1 = *(float4*)&Bs[k][tx * 8 + 4];
            float a[8] = {a0.x, a0.y, a0.z, a0.w, a1.x, a1.y, a1.z, a1.w};
            float b[8] = {b0.x, b0.y, b0.z, b0.w, b1.x, b1.y, b1.z, b1.w};
#pragma unroll
            for (int y = 0; y < 8; y++)
#pragma unroll
                for (int xx = 0; xx < 8; xx++)
                    acc[y][xx] = fmaf(a[y], b[xx], acc[y][xx]);
        }
        __syncthreads();
    }

    const float scale = 0.03125f;  // 1/sqrt(1024)
#pragma unroll
    for (int y = 0; y < 8; y++) {
        int row = row0 + ty * 8 + y;
        float* dst = g_S + (size_t)row * N_TOKEN + col0 + tx * 8;
        float4 o0 = {acc[y][0] * scale, acc[y][1] * scale, acc[y][2] * scale, acc[y][3] * scale};
        float4 o1 = {acc[y][4] * scale, acc[y][5] * scale, acc[y][6] * scale, acc[y][7] * scale};
        *(float4*)dst       = o0;
        *(float4*)(dst + 4) = o1;
    }
}

// ---------------------------------------------------------------------------
// Kernel 3: in-place causal row softmax. Row i valid length = i+1; tail -> 0.
// ---------------------------------------------------------------------------
__global__ __launch_bounds__(256) void softmax_kernel()
{
    __shared__ float red[256];
    const int i     = blockIdx.x;
    const int valid = i + 1;
    const int tid   = threadIdx.x;
    float* row = g_S + (size_t)i * N_TOKEN;

    // pass 1: max
    float m = -1e30f;
    for (int j = tid; j < valid; j += 256) m = fmaxf(m, row[j]);
    red[tid] = m; __syncthreads();
    for (int s = 128; s > 0; s >>= 1) {
        if (tid < s) red[tid] = fmaxf(red[tid], red[tid + s]);
        __syncthreads();
    }
    m = red[0]; __syncthreads();

    // pass 2: exp + sum (each j owned by one thread across passes)
    float sum = 0.f;
    for (int j = tid; j < valid; j += 256) {
        float e = __expf(row[j] - m);
        row[j] = e;
        sum += e;
    }
    red[tid] = sum; __syncthreads();
    for (int s = 128; s > 0; s >>= 1) {
        if (tid < s) red[tid] += red[tid + s];
        __syncthreads();
    }
    float inv = 1.0f / red[0];

    // pass 3: normalize + zero masked tail (so PV GEMM needs no masking)
    for (int j = tid; j < valid; j += 256) row[j] *= inv;
    for (int j = valid + tid; j < N_TOKEN; j += 256) row[j] = 0.f;
}

// ---------------------------------------------------------------------------
// Kernel 4: O = P @ V  (NN GEMM, K-loop capped at (rt+1)*128 by causality)
// ---------------------------------------------------------------------------
__global__ __launch_bounds__(256) void av_kernel(float* __restrict__ out)
{
    __shared__ float As[BK][BM + PAD];
    __shared__ float Bs[BK][BN + PAD];

    const int rt   = blockIdx.y;
    const int row0 = rt * BM;
    const int col0 = blockIdx.x * BN;
    const int kmax = (rt + 1) * BM;       // P[i][j]==0 beyond this
    const int tid  = threadIdx.x;
    const int tx   = tid & 15;
    const int ty   = tid >> 4;

    float acc[8][8];
#pragma unroll
    for (int y = 0; y < 8; y++)
#pragma unroll
        for (int xx = 0; xx < 8; xx++) acc[y][xx] = 0.f;

    for (int k0 = 0; k0 < kmax; k0 += BK) {
#pragma unroll
        for (int i = 0; i < 2; i++) {
            int idx = tid + i * 256;
            int r   = idx >> 2;
            int kq  = idx & 3;
            float4 v = *(const float4*)(g_S + (size_t)(row0 + r) * N_TOKEN + k0 + kq * 4);
            As[kq * 4 + 0][r] = v.x;
            As[kq * 4 + 1][r] = v.y;
            As[kq * 4 + 2][r] = v.z;
            As[kq * 4 + 3][r] = v.w;
        }
#pragma unroll
        for (int i = 0; i < 2; i++) {
            int idx = tid + i * 256;
            int kk  = idx >> 5;
            int cq  = idx & 31;
            *(float4*)&Bs[kk][cq * 4] =
                *(const float4*)(g_V + (size_t)(k0 + kk) * DIM + col0 + cq * 4);
        }
        __syncthreads();

#pragma unroll
        for (int k = 0; k < BK; k++) {
            float4 a0 = *(float4*)&As[k][ty * 8];
            float4 a1 = *(float4*)&As[k][ty * 8 + 4];
            float4 b0 = *(float4*)&Bs[k][tx * 8];
            float4 b1 = *(float4*)&Bs[k][tx * 8 + 4];
            float a[8] = {a0.x, a0.y, a0.z, a0.w, a1.x, a1.y, a1.z, a1.w};
            float b[8] = {b0.x, b0.y, b0.z, b0.w, b1.x, b1.y, b1.z, b1.w};
#pragma unroll
            for (int y = 0; y < 8; y++)
#pragma unroll
                for (int xx = 0; xx < 8; xx++)
                    acc[y][xx] = fmaf(a[y], b[xx], acc[y][xx]);
        }
        __syncthreads();
    }

#pragma unroll
    for (int y = 0; y < 8; y++) {
        int row = row0 + ty * 8 + y;
        float* dst = out + (size_t)row * DIM + col0 + tx * 8;
        *(float4*)dst       = make_float4(acc[y][0], acc[y][1], acc[y][2], acc[y][3]);
        *(float4*)(dst + 4) = make_float4(acc[y][4], acc[y][5], acc[y][6], acc[y][7]);
    }
}

// ---------------------------------------------------------------------------
extern "C" void kernel_launch(void* const* d_in, const int* in_sizes, int n_in,
                              void* d_out, int out_size)
{
    const float* x  = (const float*)d_in[0];
    const float* Wq = (const float*)d_in[1];
    const float* bq = (const float*)d_in[2];
    const float* Wk = (const float*)d_in[3];
    const float* bk = (const float*)d_in[4];
    const float* Wv = (const float*)d_in[5];
    const float* bv = (const float*)d_in[6];
    float* out = (float*)d_out;

    proj_kernel<<<dim3(DIM / BN, N_TOKEN / BM, 3), 256>>>(x, Wq, bq, Wk, bk, Wv, bv);
    score_kernel<<<dim3(N_TOKEN / BN, N_TOKEN / BM), 256>>>();
    softmax_kernel<<<N_TOKEN, 256>>>();
    av_kernel<<<dim3(DIM / BN, N_TOKEN / BM), 256>>>(out);
}

// round 3
// speedup vs baseline: 3.4081x; 3.4081x over previous
#include <cuda_runtime.h>
#include <cstdint>

#define NT 4096
#define DI 1024

// ---- scratch (__device__ globals per allocation rules) ----
__device__ float g_X[NT * DI];            // tf32-rounded x
__device__ float g_Q[NT * DI];            // tf32-rounded
__device__ float g_K[NT * DI];            // tf32-rounded
__device__ float g_V[NT * DI];            // full fp32
__device__ float g_Vt[DI * NT];           // tf32-rounded V^T
__device__ float g_WT[3 * DI * DI];       // tf32-rounded W^T
__device__ float g_S[(size_t)NT * NT];    // scores (f32) -> probs (tf32-rounded)

// ============================ helpers ============================
__device__ __forceinline__ uint32_t smem_u32(const void* p) {
    uint32_t a;
    asm("{ .reg .u64 t; cvta.to.shared.u64 t, %1; cvt.u32.u64 %0, t; }" : "=r"(a) : "l"(p));
    return a;
}
__device__ __forceinline__ float tf32r(float f) {
    uint32_t o;
    asm("cvt.rna.tf32.f32 %0, %1;" : "=r"(o) : "f"(f));
    return __uint_as_float(o);
}
__device__ __forceinline__ void cp16(uint32_t saddr, const void* g) {
    asm volatile("cp.async.cg.shared.global [%0], [%1], 16;" :: "r"(saddr), "l"(g));
}
__device__ __forceinline__ void cp_commit() { asm volatile("cp.async.commit_group;"); }
__device__ __forceinline__ void cp_wait1() { asm volatile("cp.async.wait_group 1;" ::: "memory"); }

__device__ __forceinline__ void mma_tf32(float* c, const uint32_t* a, const uint32_t* b) {
    asm volatile(
        "mma.sync.aligned.m16n8k8.row.col.f32.tf32.tf32.f32 "
        "{%0,%1,%2,%3}, {%4,%5,%6,%7}, {%8,%9}, {%0,%1,%2,%3};"
        : "+f"(c[0]), "+f"(c[1]), "+f"(c[2]), "+f"(c[3])
        : "r"(a[0]), "r"(a[1]), "r"(a[2]), "r"(a[3]), "r"(b[0]), "r"(b[1]));
}

// ============================ GEMM config ============================
#define BM 128
#define BN 128
#define BK 32
#define SSTR 36                     // 32 + 4 pad (keeps 16B align, conflict-free frags)
#define TILE_FLTS (BM * SSTR)       // 4608 floats per operand tile
#define STAGE_FLTS (2 * TILE_FLTS)  // 9216
#define SMEM_BYTES (2 * STAGE_FLTS * 4)  // 73728

__device__ __forceinline__ void load_tiles(
    uint32_t sA, uint32_t sB,
    const float* __restrict__ A, int lda,
    const float* __restrict__ B, int ldb,
    int row0, int col0, int k0, int tid)
{
#pragma unroll
    for (int i = 0; i < 4; i++) {
        int idx = tid + i * 256;            // 0..1023 : 128 rows x 8 x 16B
        int r = idx >> 3, kq = idx & 7;
        cp16(sA + (uint32_t)(r * SSTR + kq * 4) * 4,
             A + (size_t)(row0 + r) * lda + k0 + kq * 4);
    }
#pragma unroll
    for (int i = 0; i < 4; i++) {
        int idx = tid + i * 256;
        int r = idx >> 3, kq = idx & 7;
        cp16(sB + (uint32_t)(r * SSTR + kq * 4) * 4,
             B + (size_t)(col0 + r) * ldb + k0 + kq * 4);
    }
    cp_commit();
}

// D[row0:+128, col0:+128] = A[row0:, :kLen] * B[col0:, :kLen]^T  (both K-major)
__device__ __forceinline__ void gemm_tile(
    const float* __restrict__ A, int lda,
    const float* __restrict__ B, int ldb,
    int row0, int col0, int kLen,
    float scale, const float* __restrict__ bias, bool rnd,
    float* __restrict__ Out, int ldo)
{
    extern __shared__ float sm[];
    const uint32_t sb = smem_u32(sm);
    const int tid  = threadIdx.x;
    const int lane = tid & 31;
    const int warp = tid >> 5;
    const int wm = warp >> 2;       // 0..1
    const int wn = warp & 3;        // 0..3

    float acc[4][4][4];
#pragma unroll
    for (int mi = 0; mi < 4; mi++)
#pragma unroll
        for (int ni = 0; ni < 4; ni++)
#pragma unroll
            for (int q = 0; q < 4; q++) acc[mi][ni][q] = 0.f;

    const int nStages = kLen / BK;
    const uint32_t stB = STAGE_FLTS * 4;
    load_tiles(sb, sb + TILE_FLTS * 4, A, lda, B, ldb, row0, col0, 0, tid);
    load_tiles(sb + stB, sb + stB + TILE_FLTS * 4, A, lda, B, ldb, row0, col0, BK, tid);

    for (int s = 0; s < nStages; s++) {
        cp_wait1();
        __syncthreads();
        const float* As_ = sm + (s & 1) * STAGE_FLTS;
        const float* Bs_ = As_ + TILE_FLTS;
#pragma unroll
        for (int k8 = 0; k8 < 4; k8++) {
            const int kb = k8 * 8 + (lane & 3);
            uint32_t af[4][4], bf[4][2];
#pragma unroll
            for (int mi = 0; mi < 4; mi++) {
                const int r = wm * 64 + mi * 16 + (lane >> 2);
                af[mi][0] = __float_as_uint(As_[r * SSTR + kb]);
                af[mi][1] = __float_as_uint(As_[(r + 8) * SSTR + kb]);
                af[mi][2] = __float_as_uint(As_[r * SSTR + kb + 4]);
                af[mi][3] = __float_as_uint(As_[(r + 8) * SSTR + kb + 4]);
            }
#pragma unroll
            for (int ni = 0; ni < 4; ni++) {
                const int c = wn * 32 + ni * 8 + (lane >> 2);
                bf[ni][0] = __float_as_uint(Bs_[c * SSTR + kb]);
                bf[ni][1] = __float_as_uint(Bs_[c * SSTR + kb + 4]);
            }
#pragma unroll
            for (int mi = 0; mi < 4; mi++)
#pragma unroll
                for (int ni = 0; ni < 4; ni++)
                    mma_tf32(acc[mi][ni], af[mi], bf[ni]);
        }
        __syncthreads();
        if (s + 2 < nStages) {
            const uint32_t so = ((s) & 1) * stB;
            load_tiles(sb + so, sb + so + TILE_FLTS * 4, A, lda, B, ldb,
                       row0, col0, (s + 2) * BK, tid);
        } else {
            cp_commit();   // empty group keeps wait_group accounting constant
        }
    }

    // epilogue
#pragma unroll
    for (int mi = 0; mi < 4; mi++) {
#pragma unroll
        for (int ni = 0; ni < 4; ni++) {
            const int row = row0 + wm * 64 + mi * 16 + (lane >> 2);
            const int col = col0 + wn * 32 + ni * 8 + 2 * (lane & 3);
            float2 v0 = make_float2(acc[mi][ni][0] * scale, acc[mi][ni][1] * scale);
            float2 v1 = make_float2(acc[mi][ni][2] * scale, acc[mi][ni][3] * scale);
            if (bias) {
                const float b0 = bias[col], b1 = bias[col + 1];
                v0.x += b0; v0.y += b1;
                v1.x += b0; v1.y += b1;
            }
            if (rnd) {
                v0.x = tf32r(v0.x); v0.y = tf32r(v0.y);
                v1.x = tf32r(v1.x); v1.y = tf32r(v1.y);
            }
            *(float2*)(Out + (size_t)row * ldo + col)       = v0;
            *(float2*)(Out + (size_t)(row + 8) * ldo + col) = v1;
        }
    }
}

// ============================ kernels ============================
__global__ __launch_bounds__(256) void proj_k(
    const float* __restrict__ bq, const float* __restrict__ bk, const float* __restrict__ bv)
{
    const int z = blockIdx.z;
    const float* bias = (z == 0) ? bq : (z == 1) ? bk : bv;
    float* out = (z == 0) ? g_Q : (z == 1) ? g_K : g_V;
    gemm_tile(g_X, DI, g_WT + (size_t)z * DI * DI, DI,
              blockIdx.y * BM, blockIdx.x * BN, DI, 1.0f, bias, z < 2, out, DI);
}

__global__ __launch_bounds__(256) void score_k()
{
    int b = blockIdx.x, rt = 0;
    while (b > rt) { b -= rt + 1; rt++; }
    gemm_tile(g_Q, DI, g_K, DI, rt * BM, b * BN, DI, 0.03125f, nullptr, false, g_S, NT);
}

__global__ __launch_bounds__(256) void av_k(float* __restrict__ out)
{
    const int rt = 31 - blockIdx.y;   // heavy rows first
    gemm_tile(g_S, NT, g_Vt, NT, rt * BM, blockIdx.x * BN, (rt + 1) * BM,
              1.0f, nullptr, false, out, DI);
}

__global__ void round_x_k(const float* __restrict__ x)
{
    const int i = blockIdx.x * blockDim.x + threadIdx.x;   // float4 index
    float4 v = ((const float4*)x)[i];
    v.x = tf32r(v.x); v.y = tf32r(v.y); v.z = tf32r(v.z); v.w = tf32r(v.w);
    ((float4*)g_X)[i] = v;
}

__global__ void transW_k(const float* __restrict__ Wq, const float* __restrict__ Wk,
                         const float* __restrict__ Wv)
{
    const float* in = (blockIdx.z == 0) ? Wq : (blockIdx.z == 1) ? Wk : Wv;
    float* out = g_WT + (size_t)blockIdx.z * DI * DI;
    __shared__ float t[32][33];
    const int c0 = blockIdx.x * 32, r0 = blockIdx.y * 32;
    const int tx = threadIdx.x, ty = threadIdx.y;
#pragma unroll
    for (int j = 0; j < 32; j += 8) t[ty + j][tx] = in[(size_t)(r0 + ty + j) * DI + c0 + tx];
    __syncthreads();
#pragma unroll
    for (int j = 0; j < 32; j += 8)
        out[(size_t)(c0 + ty + j) * DI + r0 + tx] = tf32r(t[tx][ty + j]);
}

__global__ void transV_k()
{
    __shared__ float t[32][33];
    const int c0 = blockIdx.x * 32, r0 = blockIdx.y * 32;  // r over 4096, c over 1024
    const int tx = threadIdx.x, ty = threadIdx.y;
#pragma unroll
    for (int j = 0; j < 32; j += 8) t[ty + j][tx] = g_V[(size_t)(r0 + ty + j) * DI + c0 + tx];
    __syncthreads();
#pragma unroll
    for (int j = 0; j < 32; j += 8)
        g_Vt[(size_t)(c0 + ty + j) * NT + r0 + tx] = tf32r(t[tx][ty + j]);
}

// causal row softmax, row cached in SMEM; writes tf32-rounded probs, zero tail
__global__ __launch_bounds__(256) void softmax_k()
{
    __shared__ float buf[NT];
    __shared__ float red[256];
    const int i = blockIdx.x;
    const int valid = i + 1;
    const int tid = threadIdx.x;
    float* row = g_S + (size_t)i * NT;

    float m = -1e30f;
    for (int j = tid; j < valid; j += 256) {
        float v = row[j];
        buf[j] = v;
        m = fmaxf(m, v);
    }
    red[tid] = m; __syncthreads();
    for (int s = 128; s > 0; s >>= 1) { if (tid < s) red[tid] = fmaxf(red[tid], red[tid + s]); __syncthreads(); }
    m = red[0]; __syncthreads();

    float sum = 0.f;
    for (int j = tid; j < valid; j += 256) {
        float e = __expf(buf[j] - m);
        buf[j] = e;
        sum += e;
    }
    red[tid] = sum; __syncthreads();
    for (int s = 128; s > 0; s >>= 1) { if (tid < s) red[tid] += red[tid + s]; __syncthreads(); }
    const float inv = 1.0f / red[0];
    __syncthreads();

    for (int j = tid; j < valid; j += 256) row[j] = tf32r(buf[j] * inv);
    for (int j = valid + tid; j < NT; j += 256) row[j] = 0.f;
}

// ============================ launch ============================
extern "C" void kernel_launch(void* const* d_in, const int* in_sizes, int n_in,
                              void* d_out, int out_size)
{
    const float* x  = (const float*)d_in[0];
    const float* Wq = (const float*)d_in[1];
    const float* bq = (const float*)d_in[2];
    const float* Wk = (const float*)d_in[3];
    const float* bk = (const float*)d_in[4];
    const float* Wv = (const float*)d_in[5];
    const float* bv = (const float*)d_in[6];
    float* out = (float*)d_out;

    cudaFuncSetAttribute(proj_k,  cudaFuncAttributeMaxDynamicSharedMemorySize, SMEM_BYTES);
    cudaFuncSetAttribute(score_k, cudaFuncAttributeMaxDynamicSharedMemorySize, SMEM_BYTES);
    cudaFuncSetAttribute(av_k,    cudaFuncAttributeMaxDynamicSharedMemorySize, SMEM_BYTES);

    round_x_k<<<NT * DI / 4 / 256, 256>>>(x);
    transW_k<<<dim3(32, 32, 3), dim3(32, 8)>>>(Wq, Wk, Wv);
    proj_k<<<dim3(8, 32, 3), 256, SMEM_BYTES>>>(bq, bk, bv);
    transV_k<<<dim3(32, 128), dim3(32, 8)>>>();
    score_k<<<528, 256, SMEM_BYTES>>>();
    softmax_k<<<NT, 256>>>();
    av_k<<<dim3(8, 32), 256, SMEM_BYTES>>>(out);
}

// round 4
// speedup vs baseline: 3.5676x; 1.0468x over previous
#include <cuda_runtime.h>
#include <cstdint>

#define NT 4096
#define DI 1024

// ---- scratch (__device__ globals per allocation rules) ----
__device__ float g_X[NT * DI];            // tf32-rounded x
__device__ float g_Q[NT * DI];            // tf32-rounded
__device__ float g_K[NT * DI];            // tf32-rounded
__device__ float g_V[NT * DI];            // full fp32
__device__ float g_Vt[DI * NT];           // tf32-rounded V^T
__device__ float g_WT[3 * DI * DI];       // tf32-rounded W^T
__device__ float g_S[(size_t)NT * NT];    // scores (f32) -> probs (tf32-rounded)

// ============================ helpers ============================
__device__ __forceinline__ float tf32r(float f) {
    uint32_t o;
    asm("cvt.rna.tf32.f32 %0, %1;" : "=r"(o) : "f"(f));
    return __uint_as_float(o);
}
__device__ __forceinline__ uint32_t smem_u32(const void* p) {
    uint32_t a;
    asm("{ .reg .u64 t; cvta.to.shared.u64 t, %1; cvt.u32.u64 %0, t; }" : "=r"(a) : "l"(p));
    return a;
}
__device__ __forceinline__ void cp16(uint32_t saddr, const void* g) {
    asm volatile("cp.async.cg.shared.global [%0], [%1], 16;" :: "r"(saddr), "l"(g));
}
__device__ __forceinline__ void cp_commit() { asm volatile("cp.async.commit_group;"); }
__device__ __forceinline__ void cp_wait2() { asm volatile("cp.async.wait_group 2;" ::: "memory"); }

__device__ __forceinline__ void mma_tf32(float* c, const uint32_t* a, const uint32_t* b) {
    asm volatile(
        "mma.sync.aligned.m16n8k8.row.col.f32.tf32.tf32.f32 "
        "{%0,%1,%2,%3}, {%4,%5,%6,%7}, {%8,%9}, {%0,%1,%2,%3};"
        : "+f"(c[0]), "+f"(c[1]), "+f"(c[2]), "+f"(c[3])
        : "r"(a[0]), "r"(a[1]), "r"(a[2]), "r"(a[3]), "r"(b[0]), "r"(b[1]));
}

// ============================ GEMM config ============================
#define BM 128
#define BK 32
#define SSTR 36                     // 32 + 4 pad: frag LDS conflict-free, 16B aligned

// Templated on NI = N-fragments per warp (warp tile = 64 x NI*8).
// CTA tile = 128 x (NI*32). 8 warps: wm = warp>>2 (2 in M), wn = warp&3 (4 in N).
// 3-stage cp.async pipeline.
template <int NI>
__device__ __forceinline__ void gemm_tile(
    const float* __restrict__ A, int lda,
    const float* __restrict__ B, int ldb,
    int row0, int col0, int kLen,
    float scale, const float* __restrict__ bias, bool rnd,
    float* __restrict__ Out, int ldo)
{
    constexpr int BN = NI * 32;
    constexpr int A_FLTS = BM * SSTR;
    constexpr int STAGE_FLTS = (BM + BN) * SSTR;

    extern __shared__ float sm[];
    const uint32_t sb = smem_u32(sm);
    const int tid  = threadIdx.x;
    const int lane = tid & 31;
    const int warp = tid >> 5;
    const int wm = warp >> 2;       // 0..1
    const int wn = warp & 3;        // 0..3

    float acc[4][NI][4];
#pragma unroll
    for (int mi = 0; mi < 4; mi++)
#pragma unroll
        for (int ni = 0; ni < NI; ni++)
#pragma unroll
            for (int q = 0; q < 4; q++) acc[mi][ni][q] = 0.f;

    const int nStages = kLen / BK;

    // loader: stage -> buffer (stage % 3)
    auto load_stage = [&](int s) {
        const uint32_t base = sb + (uint32_t)((s % 3) * STAGE_FLTS) * 4;
        const int k0 = s * BK;
        // A: 128 rows x 8 chunks of 16B
#pragma unroll
        for (int i = 0; i < 4; i++) {
            int idx = tid + i * 256;
            int r = idx >> 3, kq = idx & 7;
            cp16(base + (uint32_t)(r * SSTR + kq * 4) * 4,
                 A + (size_t)(row0 + r) * lda + k0 + kq * 4);
        }
        // B: BN rows x 8 chunks
#pragma unroll
        for (int i = 0; i < BN / 32; i++) {
            int idx = tid + i * 256;
            int r = idx >> 3, kq = idx & 7;
            cp16(base + (uint32_t)(A_FLTS + r * SSTR + kq * 4) * 4,
                 B + (size_t)(col0 + r) * ldb + k0 + kq * 4);
        }
        cp_commit();
    };

    load_stage(0);
    load_stage(1);
    load_stage(2);   // nStages >= 3 always (min av kLen = 128 -> 4 stages)

    for (int s = 0; s < nStages; s++) {
        cp_wait2();
        __syncthreads();
        const float* As_ = sm + (s % 3) * STAGE_FLTS;
        const float* Bs_ = As_ + A_FLTS;
#pragma unroll
        for (int k8 = 0; k8 < 4; k8++) {
            const int kb = k8 * 8 + (lane & 3);
            uint32_t af[4][4], bf[NI][2];
#pragma unroll
            for (int mi = 0; mi < 4; mi++) {
                const int r = wm * 64 + mi * 16 + (lane >> 2);
                af[mi][0] = __float_as_uint(As_[r * SSTR + kb]);
                af[mi][1] = __float_as_uint(As_[(r + 8) * SSTR + kb]);
                af[mi][2] = __float_as_uint(As_[r * SSTR + kb + 4]);
                af[mi][3] = __float_as_uint(As_[(r + 8) * SSTR + kb + 4]);
            }
#pragma unroll
            for (int ni = 0; ni < NI; ni++) {
                const int c = wn * (NI * 8) + ni * 8 + (lane >> 2);
                bf[ni][0] = __float_as_uint(Bs_[c * SSTR + kb]);
                bf[ni][1] = __float_as_uint(Bs_[c * SSTR + kb + 4]);
            }
#pragma unroll
            for (int mi = 0; mi < 4; mi++)
#pragma unroll
                for (int ni = 0; ni < NI; ni++)
                    mma_tf32(acc[mi][ni], af[mi], bf[ni]);
        }
        __syncthreads();   // all warps done with buffer before overwrite
        if (s + 3 < nStages) load_stage(s + 3);
        else cp_commit();  // empty group keeps wait accounting constant
    }

    // epilogue
#pragma unroll
    for (int mi = 0; mi < 4; mi++) {
#pragma unroll
        for (int ni = 0; ni < NI; ni++) {
            const int row = row0 + wm * 64 + mi * 16 + (lane >> 2);
            const int col = col0 + wn * (NI * 8) + ni * 8 + 2 * (lane & 3);
            float2 v0 = make_float2(acc[mi][ni][0] * scale, acc[mi][ni][1] * scale);
            float2 v1 = make_float2(acc[mi][ni][2] * scale, acc[mi][ni][3] * scale);
            if (bias) {
                const float b0 = bias[col], b1 = bias[col + 1];
                v0.x += b0; v0.y += b1;
                v1.x += b0; v1.y += b1;
            }
            if (rnd) {
                v0.x = tf32r(v0.x); v0.y = tf32r(v0.y);
                v1.x = tf32r(v1.x); v1.y = tf32r(v1.y);
            }
            *(float2*)(Out + (size_t)row * ldo + col)       = v0;
            *(float2*)(Out + (size_t)(row + 8) * ldo + col) = v1;
        }
    }
}

#define SMEM8 (3 * (BM + 256) * SSTR * 4)   // 165888 B
#define SMEM4 (3 * (BM + 128) * SSTR * 4)   // 110592 B

// ============================ kernels ============================
__global__ __launch_bounds__(256, 1) void proj_k(
    const float* __restrict__ bq, const float* __restrict__ bk, const float* __restrict__ bv)
{
    const int z = blockIdx.z;
    const float* bias = (z == 0) ? bq : (z == 1) ? bk : bv;
    float* out = (z == 0) ? g_Q : (z == 1) ? g_K : g_V;
    gemm_tile<8>(g_X, DI, g_WT + (size_t)z * DI * DI, DI,
                 blockIdx.y * BM, blockIdx.x * 256, DI, 1.0f, bias, z < 2, out, DI);
}

__global__ __launch_bounds__(256, 1) void score_k()
{
    // lower-tri 128x256 blocks: count(rt) = rt/2 + 1, total 272
    int b = blockIdx.x, rt = 0;
    while (b >= (rt >> 1) + 1) { b -= (rt >> 1) + 1; rt++; }
    gemm_tile<8>(g_Q, DI, g_K, DI, rt * BM, b * 256, DI, 0.03125f, nullptr, false, g_S, NT);
}

__global__ __launch_bounds__(256, 1) void av_k(float* __restrict__ out)
{
    const int rt = 31 - blockIdx.y;   // heavy rows first
    gemm_tile<4>(g_S, NT, g_Vt, NT, rt * BM, blockIdx.x * 128, (rt + 1) * BM,
                 1.0f, nullptr, false, out, DI);
}

__global__ void round_x_k(const float* __restrict__ x)
{
    const int i = blockIdx.x * blockDim.x + threadIdx.x;   // float4 index
    float4 v = ((const float4*)x)[i];
    v.x = tf32r(v.x); v.y = tf32r(v.y); v.z = tf32r(v.z); v.w = tf32r(v.w);
    ((float4*)g_X)[i] = v;
}

__global__ void transW_k(const float* __restrict__ Wq, const float* __restrict__ Wk,
                         const float* __restrict__ Wv)
{
    const float* in = (blockIdx.z == 0) ? Wq : (blockIdx.z == 1) ? Wk : Wv;
    float* out = g_WT + (size_t)blockIdx.z * DI * DI;
    __shared__ float t[32][33];
    const int c0 = blockIdx.x * 32, r0 = blockIdx.y * 32;
    const int tx = threadIdx.x, ty = threadIdx.y;
#pragma unroll
    for (int j = 0; j < 32; j += 8) t[ty + j][tx] = in[(size_t)(r0 + ty + j) * DI + c0 + tx];
    __syncthreads();
#pragma unroll
    for (int j = 0; j < 32; j += 8)
        out[(size_t)(c0 + ty + j) * DI + r0 + tx] = tf32r(t[tx][ty + j]);
}

__global__ void transV_k()
{
    __shared__ float t[32][33];
    const int c0 = blockIdx.x * 32, r0 = blockIdx.y * 32;  // r over 4096, c over 1024
    const int tx = threadIdx.x, ty = threadIdx.y;
#pragma unroll
    for (int j = 0; j < 32; j += 8) t[ty + j][tx] = g_V[(size_t)(r0 + ty + j) * DI + c0 + tx];
    __syncthreads();
#pragma unroll
    for (int j = 0; j < 32; j += 8)
        g_Vt[(size_t)(c0 + ty + j) * NT + r0 + tx] = tf32r(t[tx][ty + j]);
}

// causal row softmax, row cached in SMEM; writes tf32-rounded probs, zero tail
__global__ __launch_bounds__(256) void softmax_k()
{
    __shared__ float buf[NT];
    __shared__ float red[256];
    const int i = blockIdx.x;
    const int valid = i + 1;
    const int tid = threadIdx.x;
    float* row = g_S + (size_t)i * NT;

    float m = -1e30f;
    for (int j = tid; j < valid; j += 256) {
        float v = row[j];
        buf[j] = v;
        m = fmaxf(m, v);
    }
    red[tid] = m; __syncthreads();
    for (int s = 128; s > 0; s >>= 1) { if (tid < s) red[tid] = fmaxf(red[tid], red[tid + s]); __syncthreads(); }
    m = red[0]; __syncthreads();

    float sum = 0.f;
    for (int j = tid; j < valid; j += 256) {
        float e = __expf(buf[j] - m);
        buf[j] = e;
        sum += e;
    }
    red[tid] = sum; __syncthreads();
    for (int s = 128; s > 0; s >>= 1) { if (tid < s) red[tid] += red[tid + s]; __syncthreads(); }
    const float inv = 1.0f / red[0];
    __syncthreads();

    for (int j = tid; j < valid; j += 256) row[j] = tf32r(buf[j] * inv);
    for (int j = valid + tid; j < NT; j += 256) row[j] = 0.f;
}

// ============================ launch ============================
extern "C" void kernel_launch(void* const* d_in, const int* in_sizes, int n_in,
                              void* d_out, int out_size)
{
    const float* x  = (const float*)d_in[0];
    const float* Wq = (const float*)d_in[1];
    const float* bq = (const float*)d_in[2];
    const float* Wk = (const float*)d_in[3];
    const float* bk = (const float*)d_in[4];
    const float* Wv = (const float*)d_in[5];
    const float* bv = (const float*)d_in[6];
    float* out = (float*)d_out;

    cudaFuncSetAttribute(proj_k,  cudaFuncAttributeMaxDynamicSharedMemorySize, SMEM8);
    cudaFuncSetAttribute(score_k, cudaFuncAttributeMaxDynamicSharedMemorySize, SMEM8);
    cudaFuncSetAttribute(av_k,    cudaFuncAttributeMaxDynamicSharedMemorySize, SMEM4);

    round_x_k<<<NT * DI / 4 / 256, 256>>>(x);
    transW_k<<<dim3(32, 32, 3), dim3(32, 8)>>>(Wq, Wk, Wv);
    proj_k<<<dim3(4, 32, 3), 256, SMEM8>>>(bq, bk, bv);
    transV_k<<<dim3(32, 128), dim3(32, 8)>>>();
    score_k<<<272, 256, SMEM8>>>();
    softmax_k<<<NT, 256>>>();
    av_k<<<dim3(8, 32), 256, SMEM4>>>(out);
}

// round 5
// speedup vs baseline: 6.1116x; 1.7131x over previous
#include <cuda_runtime.h>
#include <cuda_fp16.h>
#include <cstdint>

#define NT 4096
#define DI 1024

// ---- scratch (__device__ globals per allocation rules) ----
__device__ __half g_X[NT * DI];           // fp16 x
__device__ __half g_Q[NT * DI];           // fp16 Q
__device__ __half g_K[NT * DI];           // fp16 K
__device__ float  g_V[NT * DI];           // fp32 V (pre-transpose)
__device__ __half g_Vt[DI * NT];          // fp16 V^T
__device__ __half g_WT[3 * DI * DI];      // fp16 W^T
__device__ float  g_S[(size_t)NT * NT];   // fp32 scores
__device__ __half g_P[(size_t)NT * NT];   // fp16 probs (zero-padded tail)

// ============================ helpers ============================
__device__ __forceinline__ uint32_t smem_u32(const void* p) {
    uint32_t a;
    asm("{ .reg .u64 t; cvta.to.shared.u64 t, %1; cvt.u32.u64 %0, t; }" : "=r"(a) : "l"(p));
    return a;
}
__device__ __forceinline__ void cp16(uint32_t saddr, const void* g) {
    asm volatile("cp.async.cg.shared.global [%0], [%1], 16;" :: "r"(saddr), "l"(g));
}
__device__ __forceinline__ void cp_commit() { asm volatile("cp.async.commit_group;"); }
__device__ __forceinline__ void cp_wait2() { asm volatile("cp.async.wait_group 2;" ::: "memory"); }

__device__ __forceinline__ void mma_f16(float* c, const uint32_t* a, const uint32_t* b) {
    asm volatile(
        "mma.sync.aligned.m16n8k16.row.col.f32.f16.f16.f32 "
        "{%0,%1,%2,%3}, {%4,%5,%6,%7}, {%8,%9}, {%0,%1,%2,%3};"
        : "+f"(c[0]), "+f"(c[1]), "+f"(c[2]), "+f"(c[3])
        : "r"(a[0]), "r"(a[1]), "r"(a[2]), "r"(a[3]), "r"(b[0]), "r"(b[1]));
}

// SMEM tile geometry: rows of 32 halves (64B); 2 rows per 128B line;
// 16B chunks XOR-swizzled within the line by (line & 7).
// STS chunk address for (row r, chunk q in 0..3):
__device__ __forceinline__ uint32_t sw_chunk(int r, int q) {
    int line = r >> 1;
    int ch = (((r & 1) << 2) | q) ^ (line & 7);
    return (uint32_t)(line * 128 + ch * 16);
}
// LDS word address for (row r, word w in 0..15), word = 2 halves:
__device__ __forceinline__ uint32_t sw_word(int r, int w) {
    int line = r >> 1;
    int ch = (((r & 1) << 2) | (w >> 2)) ^ (line & 7);
    return (uint32_t)(line * 128 + ch * 16 + (w & 3) * 4);
}

// ============================ GEMM ============================
#define BM 128
#define BK 32
#define A_BYTES (BM * 64)               // 8192

// Warp tile = 64 x (NI*8). CTA tile = 128 x (NI*32). 8 warps (2x4).
// OutT: float (scale/bias fp32 store) or __half (fp16 store).
template <int NI, typename OutT>
__device__ __forceinline__ void gemm_tile(
    const __half* __restrict__ A, int lda,
    const __half* __restrict__ B, int ldb,
    int row0, int col0, int kLen,
    float scale, const float* __restrict__ bias,
    OutT* __restrict__ Out, int ldo)
{
    constexpr int BN = NI * 32;
    constexpr int STAGE_BYTES = A_BYTES + BN * 64;

    extern __shared__ char sm[];
    const uint32_t sb = smem_u32(sm);
    const int tid  = threadIdx.x;
    const int lane = tid & 31;
    const int warp = tid >> 5;
    const int wm = warp >> 2;       // 0..1
    const int wn = warp & 3;        // 0..3

    float acc[4][NI][4];
#pragma unroll
    for (int mi = 0; mi < 4; mi++)
#pragma unroll
        for (int ni = 0; ni < NI; ni++)
#pragma unroll
            for (int q = 0; q < 4; q++) acc[mi][ni][q] = 0.f;

    const int nStages = kLen / BK;

    auto load_stage = [&](int s) {
        const uint32_t base = sb + (uint32_t)((s % 3) * STAGE_BYTES);
        const int k0 = s * BK;
        // A: 128 rows x 4 chunks (16B = 8 halves each)
#pragma unroll
        for (int i = 0; i < 2; i++) {
            int idx = tid + i * 256;
            int r = idx >> 2, q = idx & 3;
            cp16(base + sw_chunk(r, q),
                 A + (size_t)(row0 + r) * lda + k0 + q * 8);
        }
        // B: BN rows x 4 chunks
#pragma unroll
        for (int i = 0; i < NI / 2; i++) {
            int idx = tid + i * 256;
            int r = idx >> 2, q = idx & 3;
            cp16(base + A_BYTES + sw_chunk(r, q),
                 B + (size_t)(col0 + r) * ldb + k0 + q * 8);
        }
        cp_commit();
    };

    load_stage(0);
    load_stage(1);
    load_stage(2);   // nStages >= 4 in all uses

    for (int s = 0; s < nStages; s++) {
        cp_wait2();
        __syncthreads();
        const char* As_ = sm + (s % 3) * STAGE_BYTES;
        const char* Bs_ = As_ + A_BYTES;
#pragma unroll
        for (int k16 = 0; k16 < 2; k16++) {
            const int wlo = k16 * 8 + (lane & 3);
            uint32_t af[4][4], bf[NI][2];
#pragma unroll
            for (int mi = 0; mi < 4; mi++) {
                const int r = wm * 64 + mi * 16 + (lane >> 2);
                af[mi][0] = *(const uint32_t*)(As_ + sw_word(r,     wlo));
                af[mi][1] = *(const uint32_t*)(As_ + sw_word(r + 8, wlo));
                af[mi][2] = *(const uint32_t*)(As_ + sw_word(r,     wlo + 4));
                af[mi][3] = *(const uint32_t*)(As_ + sw_word(r + 8, wlo + 4));
            }
#pragma unroll
            for (int ni = 0; ni < NI; ni++) {
                const int c = wn * (NI * 8) + ni * 8 + (lane >> 2);
                bf[ni][0] = *(const uint32_t*)(Bs_ + sw_word(c, wlo));
                bf[ni][1] = *(const uint32_t*)(Bs_ + sw_word(c, wlo + 4));
            }
#pragma unroll
            for (int mi = 0; mi < 4; mi++)
#pragma unroll
                for (int ni = 0; ni < NI; ni++)
                    mma_f16(acc[mi][ni], af[mi], bf[ni]);
        }
        __syncthreads();
        if (s + 3 < nStages) load_stage(s + 3);
        else cp_commit();   // keep wait_group accounting constant
    }

    // epilogue
#pragma unroll
    for (int mi = 0; mi < 4; mi++) {
#pragma unroll
        for (int ni = 0; ni < NI; ni++) {
            const int row = row0 + wm * 64 + mi * 16 + (lane >> 2);
            const int col = col0 + wn * (NI * 8) + ni * 8 + 2 * (lane & 3);
            float v00 = acc[mi][ni][0] * scale, v01 = acc[mi][ni][1] * scale;
            float v10 = acc[mi][ni][2] * scale, v11 = acc[mi][ni][3] * scale;
            if (bias) {
                const float b0 = bias[col], b1 = bias[col + 1];
                v00 += b0; v01 += b1; v10 += b0; v11 += b1;
            }
            if (sizeof(OutT) == 2) {
                __half2* d0 = (__half2*)((__half*)Out + (size_t)row * ldo + col);
                __half2* d1 = (__half2*)((__half*)Out + (size_t)(row + 8) * ldo + col);
                *d0 = __floats2half2_rn(v00, v01);
                *d1 = __floats2half2_rn(v10, v11);
            } else {
                *(float2*)((float*)Out + (size_t)row * ldo + col)       = make_float2(v00, v01);
                *(float2*)((float*)Out + (size_t)(row + 8) * ldo + col) = make_float2(v10, v11);
            }
        }
    }
}

#define SMEM8 (3 * (A_BYTES + 256 * 64))   // 73728
#define SMEM4 (3 * (A_BYTES + 128 * 64))   // 49152

// ============================ kernels ============================
__global__ __launch_bounds__(256, 1) void projQK_k(
    const float* __restrict__ bq, const float* __restrict__ bk)
{
    const int z = blockIdx.z;
    gemm_tile<8, __half>(g_X, DI, g_WT + (size_t)z * DI * DI, DI,
                         blockIdx.y * BM, blockIdx.x * 256, DI, 1.0f,
                         z == 0 ? bq : bk, z == 0 ? g_Q : g_K, DI);
}

__global__ __launch_bounds__(256, 1) void projV_k(const float* __restrict__ bv)
{
    gemm_tile<8, float>(g_X, DI, g_WT + (size_t)2 * DI * DI, DI,
                        blockIdx.y * BM, blockIdx.x * 256, DI, 1.0f, bv, g_V, DI);
}

__global__ __launch_bounds__(256, 1) void score_k()
{
    // lower-tri 128x256 blocks: count(rt) = rt/2 + 1, total 272
    int b = blockIdx.x, rt = 0;
    while (b >= (rt >> 1) + 1) { b -= (rt >> 1) + 1; rt++; }
    gemm_tile<8, float>(g_Q, DI, g_K, DI, rt * BM, b * 256, DI, 0.03125f,
                        nullptr, g_S, NT);
}

__global__ __launch_bounds__(256) void av_k(float* __restrict__ out)
{
    const int rt = 31 - blockIdx.y;   // heavy rows first
    gemm_tile<4, float>(g_P, NT, g_Vt, NT, rt * BM, blockIdx.x * 128,
                        (rt + 1) * BM, 1.0f, nullptr, out, DI);
}

__global__ void cvt_x_k(const float* __restrict__ x)
{
    const int i = blockIdx.x * blockDim.x + threadIdx.x;   // float4 index
    float4 v = ((const float4*)x)[i];
    __half2* d = (__half2*)(g_X + i * 4);
    d[0] = __floats2half2_rn(v.x, v.y);
    d[1] = __floats2half2_rn(v.z, v.w);
}

__global__ void transW_k(const float* __restrict__ Wq, const float* __restrict__ Wk,
                         const float* __restrict__ Wv)
{
    const float* in = (blockIdx.z == 0) ? Wq : (blockIdx.z == 1) ? Wk : Wv;
    __half* out = g_WT + (size_t)blockIdx.z * DI * DI;
    __shared__ float t[32][33];
    const int c0 = blockIdx.x * 32, r0 = blockIdx.y * 32;
    const int tx = threadIdx.x, ty = threadIdx.y;
#pragma unroll
    for (int j = 0; j < 32; j += 8) t[ty + j][tx] = in[(size_t)(r0 + ty + j) * DI + c0 + tx];
    __syncthreads();
#pragma unroll
    for (int j = 0; j < 32; j += 8)
        out[(size_t)(c0 + ty + j) * DI + r0 + tx] = __float2half_rn(t[tx][ty + j]);
}

__global__ void transV_k()
{
    __shared__ float t[32][33];
    const int c0 = blockIdx.x * 32, r0 = blockIdx.y * 32;  // r over 4096, c over 1024
    const int tx = threadIdx.x, ty = threadIdx.y;
#pragma unroll
    for (int j = 0; j < 32; j += 8) t[ty + j][tx] = g_V[(size_t)(r0 + ty + j) * DI + c0 + tx];
    __syncthreads();
#pragma unroll
    for (int j = 0; j < 32; j += 8)
        g_Vt[(size_t)(c0 + ty + j) * NT + r0 + tx] = __float2half_rn(t[tx][ty + j]);
}

// causal row softmax: read fp32 S, write fp16 probs with zero tail
__global__ __launch_bounds__(256) void softmax_k()
{
    __shared__ float buf[NT];
    __shared__ float red[256];
    const int i = blockIdx.x;
    const int valid = i + 1;
    const int tid = threadIdx.x;
    const float* row = g_S + (size_t)i * NT;
    __half* prow = g_P + (size_t)i * NT;

    float m = -1e30f;
    for (int j = tid; j < valid; j += 256) {
        float v = row[j];
        buf[j] = v;
        m = fmaxf(m, v);
    }
    red[tid] = m; __syncthreads();
    for (int s = 128; s > 0; s >>= 1) { if (tid < s) red[tid] = fmaxf(red[tid], red[tid + s]); __syncthreads(); }
    m = red[0]; __syncthreads();

    float sum = 0.f;
    for (int j = tid; j < valid; j += 256) {
        float e = __expf(buf[j] - m);
        buf[j] = e;
        sum += e;
    }
    red[tid] = sum; __syncthreads();
    for (int s = 128; s > 0; s >>= 1) { if (tid < s) red[tid] += red[tid + s]; __syncthreads(); }
    const float inv = 1.0f / red[0];
    __syncthreads();

    for (int j = tid; j < valid; j += 256) prow[j] = __float2half_rn(buf[j] * inv);
    for (int j = valid + tid; j < NT; j += 256) prow[j] = __float2half_rn(0.f);
}

// ============================ launch ============================
extern "C" void kernel_launch(void* const* d_in, const int* in_sizes, int n_in,
                              void* d_out, int out_size)
{
    const float* x  = (const float*)d_in[0];
    const float* Wq = (const float*)d_in[1];
    const float* bq = (const float*)d_in[2];
    const float* Wk = (const float*)d_in[3];
    const float* bk = (const float*)d_in[4];
    const float* Wv = (const float*)d_in[5];
    const float* bv = (const float*)d_in[6];
    float* out = (float*)d_out;

    cudaFuncSetAttribute(projQK_k, cudaFuncAttributeMaxDynamicSharedMemorySize, SMEM8);
    cudaFuncSetAttribute(projV_k,  cudaFuncAttributeMaxDynamicSharedMemorySize, SMEM8);
    cudaFuncSetAttribute(score_k,  cudaFuncAttributeMaxDynamicSharedMemorySize, SMEM8);
    cudaFuncSetAttribute(av_k,     cudaFuncAttributeMaxDynamicSharedMemorySize, SMEM4);

    cvt_x_k<<<NT * DI / 4 / 256, 256>>>(x);
    transW_k<<<dim3(32, 32, 3), dim3(32, 8)>>>(Wq, Wk, Wv);
    projQK_k<<<dim3(4, 32, 2), 256, SMEM8>>>(bq, bk);
    projV_k<<<dim3(4, 32), 256, SMEM8>>>(bv);
    transV_k<<<dim3(32, 128), dim3(32, 8)>>>();
    score_k<<<272, 256, SMEM8>>>();
    softmax_k<<<NT, 256>>>();
    av_k<<<dim3(8, 32), 256, SMEM4>>>(out);
}